// round 16
// baseline (speedup 1.0000x reference)
#include <cuda_runtime.h>
#include <cuda_fp16.h>
#include <math.h>
#include <stdint.h>

#define D_MODEL 768
#define RANK 4
#define BATCH 2
#define TLEN 2048
#define MROWS (BATCH*TLEN)          // 4096
#define N1 (D_MODEL*RANK*2)         // 6144
#define KD D_MODEL                  // 768
#define NCH (D_MODEL*RANK)          // 3072
#define NCHUNK 128
#define CL (TLEN/NCHUNK)            // 16

// ---------------- scratch (static __device__, no allocations) ----------------
__device__ __half g_xh [MROWS*KD];                    // x rounded fp16
__device__ __half g_wih[N1*KD];                       // W_in  rounded fp16
__device__ __half g_woh[KD*KD];                       // W_out rounded fp16
__device__ __half g_yh [MROWS*KD];                    // y rounded fp16
__device__ __half g_u[MROWS*N1];                      // u in fp16 (48 MB)
__device__ float  g_y[MROWS*KD];
__device__ float2 g_ca[NCH], g_cb[NCH], g_cc[NCH], g_aL[NCH];
__device__ float2 g_Sloc [BATCH*NCHUNK*NCH];
__device__ float2 g_carry[BATCH*NCHUNK*NCH];

// ---------------- coefficient precompute ----------------
__global__ void coef_kernel(const float* __restrict__ ap,
                            const float* __restrict__ bp,
                            const float* __restrict__ cp) {
    int i = blockIdx.x * blockDim.x + threadIdx.x;
    if (i >= NCH) return;
    float2 a = make_float2(tanhf(ap[2*i]) * 0.97f, tanhf(ap[2*i+1]) * 0.97f);
    float2 b = make_float2(tanhf(bp[2*i]),         tanhf(bp[2*i+1]));
    float2 c = make_float2(tanhf(cp[2*i]),         tanhf(cp[2*i+1]));
    g_ca[i] = a; g_cb[i] = b; g_cc[i] = c;
    float2 p = a;
    for (int k = 1; k < CL; ++k)
        p = make_float2(p.x*a.x - p.y*a.y, p.x*a.y + p.y*a.x);
    g_aL[i] = p;
}

// ---------------- fp16 rounding of both weight matrices (one launch) --------
__global__ void round_w_kernel(const float* __restrict__ win,
                               const float* __restrict__ wout) {
    int i = blockIdx.x * 256 + threadIdx.x;
    if (i < N1*KD) {
        g_wih[i] = __float2half(win[i]);
    } else if (i < N1*KD + KD*KD) {
        int j = i - N1*KD;
        g_woh[j] = __float2half(wout[j]);
    }
}

// ---------------- RMSNorm -> fp16 ----------------
__global__ void rmsnorm_kernel(const float* __restrict__ x,
                               const float* __restrict__ w) {
    int row = blockIdx.x;
    const float* xr = x + (size_t)row * KD;
    float s = 0.f;
    for (int k = threadIdx.x; k < KD; k += 256) { float v = xr[k]; s += v * v; }
    __shared__ float red[256];
    red[threadIdx.x] = s; __syncthreads();
    for (int off = 128; off > 0; off >>= 1) {
        if (threadIdx.x < off) red[threadIdx.x] += red[threadIdx.x + off];
        __syncthreads();
    }
    float scale = rsqrtf(red[0] * (1.0f / KD) + 1e-6f);
    for (int k = threadIdx.x; k < KD; k += 256)
        g_xh[(size_t)row*KD + k] = __float2half(xr[k] * scale * w[k]);
}

// ============================================================================
// fp16 1-term GEMM, fp32 accum, mma.m16n8k16.  CTA tile 128x128, BK=32,
// 128 threads (4 warps), warp grid 2x2, WARP TILE 64x64 (8 LDSM -> 64 MMA
// per k-step).  3-stage cp.async pipeline, one barrier/k-tile, lb(128,2).
// ============================================================================
#define SRW 40                       // smem row stride in fp16 (80B)
#define SSTG (2 * 128 * SRW)         // halves per stage (A tile + B tile)
#define NSTAGE 3
#define GEMM_SMEM (NSTAGE * SSTG * 2)   // 61440 bytes

__device__ __forceinline__ void mma_f16(float* c, const uint32_t* a,
                                        uint32_t b0, uint32_t b1) {
    asm volatile(
        "mma.sync.aligned.m16n8k16.row.col.f32.f16.f16.f32 "
        "{%0,%1,%2,%3}, {%4,%5,%6,%7}, {%8,%9}, {%0,%1,%2,%3};\n"
        : "+f"(c[0]), "+f"(c[1]), "+f"(c[2]), "+f"(c[3])
        : "r"(a[0]), "r"(a[1]), "r"(a[2]), "r"(a[3]), "r"(b0), "r"(b1));
}
__device__ __forceinline__ void cpa16(uint32_t s, const void* g) {
    asm volatile("cp.async.cg.shared.global [%0], [%1], 16;\n" :: "r"(s), "l"(g));
}
__device__ __forceinline__ void ldsm4(uint32_t* r, uint32_t a) {
    asm volatile("ldmatrix.sync.aligned.m8n8.x4.shared.b16 {%0,%1,%2,%3}, [%4];"
                 : "=r"(r[0]), "=r"(r[1]), "=r"(r[2]), "=r"(r[3]) : "r"(a));
}

__device__ __forceinline__ void gemm_core64(
    const __half* __restrict__ Ah, const __half* __restrict__ Bh,
    int N, int K, float acc[4][8][4], __half* smbase)
{
    int tid  = threadIdx.x;            // 0..127
    int bm   = blockIdx.y * 128;
    int bn   = blockIdx.x * 128;
    int warp = tid >> 5, lane = tid & 31;
    int wm   = (warp & 1) * 64;
    int wn   = (warp >> 1) * 64;

    int row  = tid;                    // each thread owns one A row + one B row
    const __half* gA = Ah + (size_t)(bm + row) * K;
    const __half* gB = Bh + (size_t)(bn + row) * K;
    uint32_t smb = (uint32_t)__cvta_generic_to_shared(smbase);
    uint32_t sA = smb + (uint32_t)(row * SRW) * 2u;
    uint32_t sB = sA + 128u * SRW * 2u;

    // ldmatrix lane byte-offsets (proven formulas)
    uint32_t aoff = ((uint32_t)(wm + (lane & 15)) * SRW + (uint32_t)(lane >> 4) * 8u) * 2u;
    uint32_t boff = ((uint32_t)(wn + (lane >> 4) * 8 + (lane & 7)) * SRW
                     + (uint32_t)((lane >> 3) & 1) * 8u) * 2u;

    const int nt = K / 32;             // 24
#pragma unroll
    for (int st = 0; st < 2; ++st) {
        uint32_t off = (uint32_t)st * SSTG * 2u;
        int k0 = st * 32;
#pragma unroll
        for (int c = 0; c < 4; ++c) {
            cpa16(sA + off + (uint32_t)c * 16u, gA + k0 + c * 8);
            cpa16(sB + off + (uint32_t)c * 16u, gB + k0 + c * 8);
        }
        asm volatile("cp.async.commit_group;\n");
    }

    int cbuf = 0, ibuf = 2;
    for (int t = 0; t < nt; ++t) {
        asm volatile("cp.async.wait_group 1;\n");
        __syncthreads();

        if (t + 2 < nt) {
            uint32_t off = (uint32_t)ibuf * SSTG * 2u;
            int k0 = (t + 2) * 32;
#pragma unroll
            for (int c = 0; c < 4; ++c) {
                cpa16(sA + off + (uint32_t)c * 16u, gA + k0 + c * 8);
                cpa16(sB + off + (uint32_t)c * 16u, gB + k0 + c * 8);
            }
        }
        asm volatile("cp.async.commit_group;\n");

        uint32_t As_u = smb + (uint32_t)cbuf * SSTG * 2u;
        uint32_t Bs_u = As_u + 128u * SRW * 2u;
#pragma unroll
        for (int ks = 0; ks < 2; ++ks) {
            uint32_t kso = (uint32_t)ks * 32u;        // 16 halves
            uint32_t ah[4][4];
#pragma unroll
            for (int i = 0; i < 4; ++i)
                ldsm4(ah[i], As_u + aoff + (uint32_t)i * 16u * SRW * 2u + kso);
            uint32_t bf[4][4];
#pragma unroll
            for (int p = 0; p < 4; ++p)
                ldsm4(bf[p], Bs_u + boff + (uint32_t)p * 16u * SRW * 2u + kso);
#pragma unroll
            for (int j = 0; j < 8; ++j) {
                uint32_t bh0 = bf[j >> 1][(j & 1) * 2];
                uint32_t bh1 = bf[j >> 1][(j & 1) * 2 + 1];
#pragma unroll
                for (int i = 0; i < 4; ++i)
                    mma_f16(acc[i][j], ah[i], bh0, bh1);
            }
        }
        cbuf = (cbuf == NSTAGE - 1) ? 0 : cbuf + 1;
        ibuf = (ibuf == NSTAGE - 1) ? 0 : ibuf + 1;
    }
}

__global__ __launch_bounds__(128, 2) void gemm1_kernel() {
    extern __shared__ __half smdyn[];
    float acc[4][8][4];
#pragma unroll
    for (int i = 0; i < 4; ++i)
#pragma unroll
        for (int j = 0; j < 8; ++j)
#pragma unroll
            for (int v = 0; v < 4; ++v) acc[i][j][v] = 0.f;

    gemm_core64(g_xh, g_wih, N1, KD, acc, smdyn);

    int tid = threadIdx.x, warp = tid >> 5, lane = tid & 31;
    int wm = (warp & 1) * 64, wn = (warp >> 1) * 64;
    int g = lane >> 2, tg = lane & 3;
    int bm = blockIdx.y * 128, bn = blockIdx.x * 128;
#pragma unroll
    for (int i = 0; i < 4; ++i) {
        int r0 = bm + wm + i * 16 + g;
#pragma unroll
        for (int j = 0; j < 8; ++j) {
            int col = bn + wn + j * 8 + tg * 2;
            *(__half2*)(g_u + (size_t)r0      * N1 + col) = __floats2half2_rn(acc[i][j][0], acc[i][j][1]);
            *(__half2*)(g_u + (size_t)(r0+8)  * N1 + col) = __floats2half2_rn(acc[i][j][2], acc[i][j][3]);
        }
    }
}

__global__ __launch_bounds__(128, 2) void gemm2_kernel(float* __restrict__ out) {
    extern __shared__ __half smdyn[];
    float acc[4][8][4];
#pragma unroll
    for (int i = 0; i < 4; ++i)
#pragma unroll
        for (int j = 0; j < 8; ++j)
#pragma unroll
            for (int v = 0; v < 4; ++v) acc[i][j][v] = 0.f;

    gemm_core64(g_yh, g_woh, KD, KD, acc, smdyn);

    int tid = threadIdx.x, warp = tid >> 5, lane = tid & 31;
    int wm = (warp & 1) * 64, wn = (warp >> 1) * 64;
    int g = lane >> 2, tg = lane & 3;
    int bm = blockIdx.y * 128, bn = blockIdx.x * 128;
#pragma unroll
    for (int i = 0; i < 4; ++i) {
        int r0 = bm + wm + i * 16 + g;
#pragma unroll
        for (int j = 0; j < 8; ++j) {
            int col = bn + wn + j * 8 + tg * 2;
            *(float2*)(out + (size_t)r0      * KD + col) = make_float2(acc[i][j][0], acc[i][j][1]);
            *(float2*)(out + (size_t)(r0+8)  * KD + col) = make_float2(acc[i][j][2], acc[i][j][3]);
        }
    }
}

// ---------------- Phase A: per-chunk local scan (u fp16, prefetched) --------
__global__ void scanA_kernel() {
    int d = blockIdx.x * 256 + threadIdx.x;
    int j = blockIdx.y, b = blockIdx.z;
    int ch0 = d * RANK;
    float2 a[RANK], bb[RANK], cc[RANK], s[RANK];
#pragma unroll
    for (int r = 0; r < RANK; ++r) {
        a[r] = g_ca[ch0 + r]; bb[r] = g_cb[ch0 + r]; cc[r] = g_cc[ch0 + r];
        s[r] = make_float2(0.f, 0.f);
    }
    int t0 = j * CL;
    const uint4* up = (const uint4*)(g_u + (size_t)(b * TLEN + t0) * N1 + d * (RANK * 2));
    float* yp = g_y + (size_t)(b * TLEN + t0) * D_MODEL + d;
    uint4 v = *up;
    for (int t = 0; t < CL; ++t) {
        up += N1 / 8;
        uint4 vn;
        if (t + 1 < CL) vn = *up;
        const __half2* ph = (const __half2*)&v;
        float y = 0.f;
#pragma unroll
        for (int r = 0; r < RANK; ++r) {
            float2 uc = __half22float2(ph[r]);
            float bur = bb[r].x * uc.x - bb[r].y * uc.y;
            float bui = bb[r].x * uc.y + bb[r].y * uc.x;
            float sr  = a[r].x * s[r].x - a[r].y * s[r].y + bur;
            float si  = a[r].x * s[r].y + a[r].y * s[r].x + bui;
            s[r] = make_float2(sr, si);
            y += cc[r].x * sr - cc[r].y * si;
        }
        *yp = y;
        yp += D_MODEL;
        v = vn;
    }
    float2* sp = g_Sloc + (size_t)(b * NCHUNK + j) * NCH + ch0;
#pragma unroll
    for (int r = 0; r < RANK; ++r) sp[r] = s[r];
}

// ---------------- Phase B: sequential carry combine across chunks ----------------
__global__ void scanB_kernel() {
    int idx = blockIdx.x * 256 + threadIdx.x;
    if (idx >= BATCH * NCH) return;
    int b = idx / NCH, ch = idx % NCH;
    float2 aL = g_aL[ch];
    float2 carry = make_float2(0.f, 0.f);
    for (int j = 0; j < NCHUNK; ++j) {
        g_carry[(size_t)(b * NCHUNK + j) * NCH + ch] = carry;
        float2 S = g_Sloc[(size_t)(b * NCHUNK + j) * NCH + ch];
        carry = make_float2(aL.x * carry.x - aL.y * carry.y + S.x,
                            aL.x * carry.y + aL.y * carry.x + S.y);
    }
}

// ---------------- Phase C: y += Re(c*a^p*carry) -> fp16 yh (all chunks) -----
__global__ void scanC_kernel() {
    int d = blockIdx.x * 256 + threadIdx.x;
    int j = blockIdx.y, b = blockIdx.z;
    int ch0 = d * RANK;
    float2 a[RANK], w[RANK];
#pragma unroll
    for (int r = 0; r < RANK; ++r) {
        a[r] = g_ca[ch0 + r];
        float2 carry = g_carry[(size_t)(b * NCHUNK + j) * NCH + ch0 + r];
        float2 c = g_cc[ch0 + r];
        w[r] = make_float2(c.x * carry.x - c.y * carry.y,
                           c.x * carry.y + c.y * carry.x);
    }
    int t0 = j * CL;
    size_t idx = (size_t)(b * TLEN + t0) * D_MODEL + d;
    for (int t = 0; t < CL; ++t) {
        float corr = 0.f;
#pragma unroll
        for (int r = 0; r < RANK; ++r) {
            w[r] = make_float2(w[r].x * a[r].x - w[r].y * a[r].y,
                               w[r].x * a[r].y + w[r].y * a[r].x);
            corr += w[r].x;
        }
        g_yh[idx] = __float2half(g_y[idx] + corr);
        idx += D_MODEL;
    }
}

// ---------------- launch (no device symbols passed from host; no guards) ----
extern "C" void kernel_launch(void* const* d_in, const int* in_sizes, int n_in,
                              void* d_out, int out_size) {
    const float* x    = (const float*)d_in[0];
    const float* nw   = (const float*)d_in[1];
    const float* Win  = (const float*)d_in[2];
    const float* Wout = (const float*)d_in[3];
    const float* ap   = (const float*)d_in[4];
    const float* bp   = (const float*)d_in[5];
    const float* cp   = (const float*)d_in[6];
    float* out = (float*)d_out;

    cudaFuncSetAttribute(gemm1_kernel, cudaFuncAttributeMaxDynamicSharedMemorySize, GEMM_SMEM);
    cudaFuncSetAttribute(gemm2_kernel, cudaFuncAttributeMaxDynamicSharedMemorySize, GEMM_SMEM);

    coef_kernel<<<(NCH + 255) / 256, 256>>>(ap, bp, cp);
    round_w_kernel<<<(N1 * KD + KD * KD + 255) / 256, 256>>>(Win, Wout);
    rmsnorm_kernel<<<MROWS, 256>>>(x, nw);
    gemm1_kernel<<<dim3(N1 / 128, MROWS / 128), 128, GEMM_SMEM>>>();
    scanA_kernel<<<dim3(D_MODEL / 256, NCHUNK, BATCH), 256>>>();
    scanB_kernel<<<(BATCH * NCH + 255) / 256, 256>>>();
    scanC_kernel<<<dim3(D_MODEL / 256, NCHUNK, BATCH), 256>>>();
    gemm2_kernel<<<dim3(KD / 128, MROWS / 128), 128, GEMM_SMEM>>>(out);
}

// round 17
// speedup vs baseline: 1.1727x; 1.1727x over previous
#include <cuda_runtime.h>
#include <cuda_fp16.h>
#include <math.h>
#include <stdint.h>

#define D_MODEL 768
#define RANK 4
#define BATCH 2
#define TLEN 2048
#define MROWS (BATCH*TLEN)          // 4096
#define N1 (D_MODEL*RANK*2)         // 6144
#define KD D_MODEL                  // 768
#define NCH (D_MODEL*RANK)          // 3072
#define NCHUNK 128
#define CL (TLEN/NCHUNK)            // 16

// ---------------- scratch (static __device__, no allocations) ----------------
__device__ __half g_xh [MROWS*KD];                    // x rounded fp16
__device__ __half g_wih[N1*KD];                       // W_in  rounded fp16
__device__ __half g_woh[KD*KD];                       // W_out rounded fp16
__device__ __half g_yh [MROWS*KD];                    // y rounded fp16
__device__ __half g_u[MROWS*N1];                      // u in fp16 (48 MB)
__device__ float  g_y[MROWS*KD];
__device__ float2 g_ca[NCH], g_cb[NCH], g_cc[NCH], g_aL[NCH];
__device__ float2 g_Sloc [BATCH*NCHUNK*NCH];
__device__ float2 g_carry[BATCH*NCHUNK*NCH];

// ---------------- coefficient precompute ----------------
__global__ void coef_kernel(const float* __restrict__ ap,
                            const float* __restrict__ bp,
                            const float* __restrict__ cp) {
    int i = blockIdx.x * blockDim.x + threadIdx.x;
    if (i >= NCH) return;
    float2 a = make_float2(tanhf(ap[2*i]) * 0.97f, tanhf(ap[2*i+1]) * 0.97f);
    float2 b = make_float2(tanhf(bp[2*i]),         tanhf(bp[2*i+1]));
    float2 c = make_float2(tanhf(cp[2*i]),         tanhf(cp[2*i+1]));
    g_ca[i] = a; g_cb[i] = b; g_cc[i] = c;
    float2 p = a;
    for (int k = 1; k < CL; ++k)
        p = make_float2(p.x*a.x - p.y*a.y, p.x*a.y + p.y*a.x);
    g_aL[i] = p;
}

// ---------------- fp16 rounding of both weight matrices (one launch) --------
__global__ void round_w_kernel(const float* __restrict__ win,
                               const float* __restrict__ wout) {
    int i = blockIdx.x * 256 + threadIdx.x;
    if (i < N1*KD) {
        g_wih[i] = __float2half(win[i]);
    } else if (i < N1*KD + KD*KD) {
        int j = i - N1*KD;
        g_woh[j] = __float2half(wout[j]);
    }
}

// ---------------- RMSNorm -> fp16 ----------------
__global__ void rmsnorm_kernel(const float* __restrict__ x,
                               const float* __restrict__ w) {
    int row = blockIdx.x;
    const float* xr = x + (size_t)row * KD;
    float s = 0.f;
    for (int k = threadIdx.x; k < KD; k += 256) { float v = xr[k]; s += v * v; }
    __shared__ float red[256];
    red[threadIdx.x] = s; __syncthreads();
    for (int off = 128; off > 0; off >>= 1) {
        if (threadIdx.x < off) red[threadIdx.x] += red[threadIdx.x + off];
        __syncthreads();
    }
    float scale = rsqrtf(red[0] * (1.0f / KD) + 1e-6f);
    for (int k = threadIdx.x; k < KD; k += 256)
        g_xh[(size_t)row*KD + k] = __float2half(xr[k] * scale * w[k]);
}

// ============================================================================
// Shared GEMM building blocks
// ============================================================================
#define SRW 40                       // smem row stride in fp16 (80B)
#define NSTAGE 3

__device__ __forceinline__ void mma_f16(float* c, const uint32_t* a,
                                        uint32_t b0, uint32_t b1) {
    asm volatile(
        "mma.sync.aligned.m16n8k16.row.col.f32.f16.f16.f32 "
        "{%0,%1,%2,%3}, {%4,%5,%6,%7}, {%8,%9}, {%0,%1,%2,%3};\n"
        : "+f"(c[0]), "+f"(c[1]), "+f"(c[2]), "+f"(c[3])
        : "r"(a[0]), "r"(a[1]), "r"(a[2]), "r"(a[3]), "r"(b0), "r"(b1));
}
__device__ __forceinline__ void cpa16(uint32_t s, const void* g) {
    asm volatile("cp.async.cg.shared.global [%0], [%1], 16;\n" :: "r"(s), "l"(g));
}
__device__ __forceinline__ void ldsm4(uint32_t* r, uint32_t a) {
    asm volatile("ldmatrix.sync.aligned.m8n8.x4.shared.b16 {%0,%1,%2,%3}, [%4];"
                 : "=r"(r[0]), "=r"(r[1]), "=r"(r[2]), "=r"(r[3]) : "r"(a));
}

// ============================================================================
// gemm1: CTA tile 64x128, 256 threads, warp grid 2x4, warp tile 32x32,
// 3-stage cp.async, one barrier/k-tile, lb(256,3) -> 24 warps/SM.
// ============================================================================
#define SSTG1 ((64 + 128) * SRW)            // halves per stage
#define GEMM1_SMEM (NSTAGE * SSTG1 * 2)     // 46080 bytes

__global__ __launch_bounds__(256, 3) void gemm1_kernel() {
    extern __shared__ __half smdyn[];
    const __half* __restrict__ Ah = g_xh;
    const __half* __restrict__ Bh = g_wih;
    const int N = N1, K = KD;

    int tid  = threadIdx.x;
    int bm   = blockIdx.y * 64;
    int bn   = blockIdx.x * 128;
    int warp = tid >> 5, lane = tid & 31;
    int wm   = (warp & 1) * 32;
    int wn   = (warp >> 1) * 32;

    float acc[2][4][4];
#pragma unroll
    for (int i = 0; i < 2; ++i)
#pragma unroll
        for (int j = 0; j < 4; ++j)
#pragma unroll
            for (int v = 0; v < 4; ++v) acc[i][j][v] = 0.f;

    // load mapping: A 64 rows x 4 chunks (1/thread), B 128 rows x 4 chunks (2/thread)
    int arow = tid >> 2, achk = tid & 3;
    int brow = tid >> 1, bchk = (tid & 1) * 2;
    const __half* gA = Ah + (size_t)(bm + arow) * K + achk * 8;
    const __half* gB = Bh + (size_t)(bn + brow) * K + bchk * 8;
    uint32_t smb = (uint32_t)__cvta_generic_to_shared(smdyn);
    uint32_t sA = smb + ((uint32_t)arow * SRW + (uint32_t)achk * 8u) * 2u;
    uint32_t sB = smb + (64u * SRW + (uint32_t)brow * SRW + (uint32_t)bchk * 8u) * 2u;

    uint32_t aoff = ((uint32_t)(wm + (lane & 15)) * SRW + (uint32_t)(lane >> 4) * 8u) * 2u;
    uint32_t boff = (64u * SRW + (uint32_t)(wn + (lane >> 4) * 8 + (lane & 7)) * SRW
                     + (uint32_t)((lane >> 3) & 1) * 8u) * 2u;

    const int nt = K / 32;             // 24
#pragma unroll
    for (int st = 0; st < 2; ++st) {
        uint32_t off = (uint32_t)st * SSTG1 * 2u;
        int k0 = st * 32;
        cpa16(sA + off,      gA + k0);
        cpa16(sB + off,      gB + k0);
        cpa16(sB + off + 16, gB + k0 + 8);
        asm volatile("cp.async.commit_group;\n");
    }

    int cbuf = 0, ibuf = 2;
    for (int t = 0; t < nt; ++t) {
        asm volatile("cp.async.wait_group 1;\n");
        __syncthreads();

        if (t + 2 < nt) {
            uint32_t off = (uint32_t)ibuf * SSTG1 * 2u;
            int k0 = (t + 2) * 32;
            cpa16(sA + off,      gA + k0);
            cpa16(sB + off,      gB + k0);
            cpa16(sB + off + 16, gB + k0 + 8);
        }
        asm volatile("cp.async.commit_group;\n");

        uint32_t base = smb + (uint32_t)cbuf * SSTG1 * 2u;
#pragma unroll
        for (int ks = 0; ks < 2; ++ks) {
            uint32_t kso = (uint32_t)ks * 32u;
            uint32_t ah[2][4];
#pragma unroll
            for (int i = 0; i < 2; ++i)
                ldsm4(ah[i], base + aoff + (uint32_t)i * 16u * SRW * 2u + kso);
            uint32_t bf[2][4];
#pragma unroll
            for (int p = 0; p < 2; ++p)
                ldsm4(bf[p], base + boff + (uint32_t)p * 16u * SRW * 2u + kso);
#pragma unroll
            for (int j = 0; j < 4; ++j) {
                uint32_t bh0 = bf[j >> 1][(j & 1) * 2];
                uint32_t bh1 = bf[j >> 1][(j & 1) * 2 + 1];
#pragma unroll
                for (int i = 0; i < 2; ++i)
                    mma_f16(acc[i][j], ah[i], bh0, bh1);
            }
        }
        cbuf = (cbuf == NSTAGE - 1) ? 0 : cbuf + 1;
        ibuf = (ibuf == NSTAGE - 1) ? 0 : ibuf + 1;
    }

    int g = lane >> 2, tg = lane & 3;
#pragma unroll
    for (int i = 0; i < 2; ++i) {
        int r0 = bm + wm + i * 16 + g;
#pragma unroll
        for (int j = 0; j < 4; ++j) {
            int col = bn + wn + j * 8 + tg * 2;
            *(__half2*)(g_u + (size_t)r0      * N + col) = __floats2half2_rn(acc[i][j][0], acc[i][j][1]);
            *(__half2*)(g_u + (size_t)(r0+8)  * N + col) = __floats2half2_rn(acc[i][j][2], acc[i][j][3]);
        }
    }
}

// ============================================================================
// gemm2: R14-proven core — CTA 128x128, 256 threads, warp tile 64x32, lb(256,2)
// ============================================================================
#define SSTG (2 * 128 * SRW)
#define GEMM2_SMEM (NSTAGE * SSTG * 2)      // 61440 bytes

__global__ __launch_bounds__(256, 2) void gemm2_kernel(float* __restrict__ out) {
    extern __shared__ __half smdyn[];
    const __half* __restrict__ Ah = g_yh;
    const __half* __restrict__ Bh = g_woh;
    const int N = KD, K = KD;

    int tid  = threadIdx.x;
    int bm   = blockIdx.y * 128;
    int bn   = blockIdx.x * 128;
    int warp = tid >> 5, lane = tid & 31;
    int wm   = (warp & 1) * 64;
    int wn   = (warp >> 1) * 32;

    float acc[4][4][4];
#pragma unroll
    for (int i = 0; i < 4; ++i)
#pragma unroll
        for (int j = 0; j < 4; ++j)
#pragma unroll
            for (int v = 0; v < 4; ++v) acc[i][j][v] = 0.f;

    int row  = tid >> 1;
    int half = (tid & 1) * 16;
    const __half* gA = Ah + (size_t)(bm + row) * K + half;
    const __half* gB = Bh + (size_t)(bn + row) * K + half;
    uint32_t smb = (uint32_t)__cvta_generic_to_shared(smdyn);
    uint32_t sA = smb + (uint32_t)(row * SRW + half) * 2u;
    uint32_t sB = sA + 128u * SRW * 2u;

    uint32_t aoff = ((uint32_t)(wm + (lane & 15)) * SRW + (uint32_t)(lane >> 4) * 8u) * 2u;
    uint32_t boff = ((uint32_t)(wn + (lane >> 4) * 8 + (lane & 7)) * SRW
                     + (uint32_t)((lane >> 3) & 1) * 8u) * 2u;

    const int nt = K / 32;
#pragma unroll
    for (int st = 0; st < 2; ++st) {
        uint32_t off = (uint32_t)st * SSTG * 2u;
        int k0 = st * 32;
        cpa16(sA + off,      gA + k0);
        cpa16(sA + off + 16, gA + k0 + 8);
        cpa16(sB + off,      gB + k0);
        cpa16(sB + off + 16, gB + k0 + 8);
        asm volatile("cp.async.commit_group;\n");
    }

    int cbuf = 0, ibuf = 2;
    for (int t = 0; t < nt; ++t) {
        asm volatile("cp.async.wait_group 1;\n");
        __syncthreads();

        if (t + 2 < nt) {
            uint32_t off = (uint32_t)ibuf * SSTG * 2u;
            int k0 = (t + 2) * 32;
            cpa16(sA + off,      gA + k0);
            cpa16(sA + off + 16, gA + k0 + 8);
            cpa16(sB + off,      gB + k0);
            cpa16(sB + off + 16, gB + k0 + 8);
        }
        asm volatile("cp.async.commit_group;\n");

        uint32_t As_u = smb + (uint32_t)cbuf * SSTG * 2u;
        uint32_t Bs_u = As_u + 128u * SRW * 2u;
#pragma unroll
        for (int ks = 0; ks < 2; ++ks) {
            uint32_t kso = (uint32_t)ks * 32u;
            uint32_t ah[4][4];
#pragma unroll
            for (int i = 0; i < 4; ++i)
                ldsm4(ah[i], As_u + aoff + (uint32_t)i * 16u * SRW * 2u + kso);
            uint32_t bf[2][4];
#pragma unroll
            for (int p = 0; p < 2; ++p)
                ldsm4(bf[p], Bs_u + boff + (uint32_t)p * 16u * SRW * 2u + kso);
#pragma unroll
            for (int j = 0; j < 4; ++j) {
                uint32_t bh0 = bf[j >> 1][(j & 1) * 2];
                uint32_t bh1 = bf[j >> 1][(j & 1) * 2 + 1];
#pragma unroll
                for (int i = 0; i < 4; ++i)
                    mma_f16(acc[i][j], ah[i], bh0, bh1);
            }
        }
        cbuf = (cbuf == NSTAGE - 1) ? 0 : cbuf + 1;
        ibuf = (ibuf == NSTAGE - 1) ? 0 : ibuf + 1;
    }

    int g = lane >> 2, tg = lane & 3;
#pragma unroll
    for (int i = 0; i < 4; ++i) {
        int r0 = bm + wm + i * 16 + g;
#pragma unroll
        for (int j = 0; j < 4; ++j) {
            int col = bn + wn + j * 8 + tg * 2;
            *(float2*)(out + (size_t)r0      * KD + col) = make_float2(acc[i][j][0], acc[i][j][1]);
            *(float2*)(out + (size_t)(r0+8)  * KD + col) = make_float2(acc[i][j][2], acc[i][j][3]);
        }
    }
}

// ---------------- Phase A: per-chunk local scan (u fp16, prefetched) --------
__global__ void scanA_kernel() {
    int d = blockIdx.x * 256 + threadIdx.x;
    int j = blockIdx.y, b = blockIdx.z;
    int ch0 = d * RANK;
    float2 a[RANK], bb[RANK], cc[RANK], s[RANK];
#pragma unroll
    for (int r = 0; r < RANK; ++r) {
        a[r] = g_ca[ch0 + r]; bb[r] = g_cb[ch0 + r]; cc[r] = g_cc[ch0 + r];
        s[r] = make_float2(0.f, 0.f);
    }
    int t0 = j * CL;
    const uint4* up = (const uint4*)(g_u + (size_t)(b * TLEN + t0) * N1 + d * (RANK * 2));
    float* yp = g_y + (size_t)(b * TLEN + t0) * D_MODEL + d;
    uint4 v = *up;
    for (int t = 0; t < CL; ++t) {
        up += N1 / 8;
        uint4 vn;
        if (t + 1 < CL) vn = *up;
        const __half2* ph = (const __half2*)&v;
        float y = 0.f;
#pragma unroll
        for (int r = 0; r < RANK; ++r) {
            float2 uc = __half22float2(ph[r]);
            float bur = bb[r].x * uc.x - bb[r].y * uc.y;
            float bui = bb[r].x * uc.y + bb[r].y * uc.x;
            float sr  = a[r].x * s[r].x - a[r].y * s[r].y + bur;
            float si  = a[r].x * s[r].y + a[r].y * s[r].x + bui;
            s[r] = make_float2(sr, si);
            y += cc[r].x * sr - cc[r].y * si;
        }
        *yp = y;
        yp += D_MODEL;
        v = vn;
    }
    float2* sp = g_Sloc + (size_t)(b * NCHUNK + j) * NCH + ch0;
#pragma unroll
    for (int r = 0; r < RANK; ++r) sp[r] = s[r];
}

// ---------------- Phase B: sequential carry combine across chunks ----------------
__global__ void scanB_kernel() {
    int idx = blockIdx.x * 256 + threadIdx.x;
    if (idx >= BATCH * NCH) return;
    int b = idx / NCH, ch = idx % NCH;
    float2 aL = g_aL[ch];
    float2 carry = make_float2(0.f, 0.f);
    for (int j = 0; j < NCHUNK; ++j) {
        g_carry[(size_t)(b * NCHUNK + j) * NCH + ch] = carry;
        float2 S = g_Sloc[(size_t)(b * NCHUNK + j) * NCH + ch];
        carry = make_float2(aL.x * carry.x - aL.y * carry.y + S.x,
                            aL.x * carry.y + aL.y * carry.x + S.y);
    }
}

// ---------------- Phase C: y += Re(c*a^p*carry) -> fp16 yh (all chunks) -----
__global__ void scanC_kernel() {
    int d = blockIdx.x * 256 + threadIdx.x;
    int j = blockIdx.y, b = blockIdx.z;
    int ch0 = d * RANK;
    float2 a[RANK], w[RANK];
#pragma unroll
    for (int r = 0; r < RANK; ++r) {
        a[r] = g_ca[ch0 + r];
        float2 carry = g_carry[(size_t)(b * NCHUNK + j) * NCH + ch0 + r];
        float2 c = g_cc[ch0 + r];
        w[r] = make_float2(c.x * carry.x - c.y * carry.y,
                           c.x * carry.y + c.y * carry.x);
    }
    int t0 = j * CL;
    size_t idx = (size_t)(b * TLEN + t0) * D_MODEL + d;
    for (int t = 0; t < CL; ++t) {
        float corr = 0.f;
#pragma unroll
        for (int r = 0; r < RANK; ++r) {
            w[r] = make_float2(w[r].x * a[r].x - w[r].y * a[r].y,
                               w[r].x * a[r].y + w[r].y * a[r].x);
            corr += w[r].x;
        }
        g_yh[idx] = __float2half(g_y[idx] + corr);
        idx += D_MODEL;
    }
}

// ---------------- launch (no device symbols passed from host; no guards) ----
extern "C" void kernel_launch(void* const* d_in, const int* in_sizes, int n_in,
                              void* d_out, int out_size) {
    const float* x    = (const float*)d_in[0];
    const float* nw   = (const float*)d_in[1];
    const float* Win  = (const float*)d_in[2];
    const float* Wout = (const float*)d_in[3];
    const float* ap   = (const float*)d_in[4];
    const float* bp   = (const float*)d_in[5];
    const float* cp   = (const float*)d_in[6];
    float* out = (float*)d_out;

    cudaFuncSetAttribute(gemm1_kernel, cudaFuncAttributeMaxDynamicSharedMemorySize, GEMM1_SMEM);
    cudaFuncSetAttribute(gemm2_kernel, cudaFuncAttributeMaxDynamicSharedMemorySize, GEMM2_SMEM);

    coef_kernel<<<(NCH + 255) / 256, 256>>>(ap, bp, cp);
    round_w_kernel<<<(N1 * KD + KD * KD + 255) / 256, 256>>>(Win, Wout);
    rmsnorm_kernel<<<MROWS, 256>>>(x, nw);
    gemm1_kernel<<<dim3(N1 / 128, MROWS / 64), 256, GEMM1_SMEM>>>();
    scanA_kernel<<<dim3(D_MODEL / 256, NCHUNK, BATCH), 256>>>();
    scanB_kernel<<<(BATCH * NCH + 255) / 256, 256>>>();
    scanC_kernel<<<dim3(D_MODEL / 256, NCHUNK, BATCH), 256>>>();
    gemm2_kernel<<<dim3(KD / 128, MROWS / 128), 256, GEMM2_SMEM>>>(out);
}